// round 12
// baseline (speedup 1.0000x reference)
#include <cuda_runtime.h>

// Best-of-all-rounds combination:
//  - plain float4 loads/stores, VEC=4 (R2 had the fastest kernel, 18.34us)
//  - streaming loads issued BEFORE the M barrier so thread 0's linMt DRAM
//    load + serial FMA chain is hidden (R11)
//  - thread-0-only M = linMt^N binary exponentiation into smem (R3)
#define VEC 4

__global__ void __launch_bounds__(256) fused_kernel(
    const float4* __restrict__ x, float4* __restrict__ out, int n4,
    const float* __restrict__ linMt, const int* __restrict__ Np,
    const float* __restrict__ xs, float* __restrict__ outs, int n_pairs)
{
    __shared__ float sM[4];

    int base = (blockIdx.x * blockDim.x) * VEC + threadIdx.x;

    // 1) Issue streaming loads first — in flight while M is computed.
    float4 v[VEC];
    bool ok[VEC];
#pragma unroll
    for (int j = 0; j < VEC; j++) {
        int idx = base + j * 256;
        ok[j] = idx < n4;
        if (ok[j]) v[j] = __ldg(&x[idx]);
    }

    // 2) Thread 0 computes M = linMt^N (fp32 binary exp) into smem.
    if (threadIdx.x == 0) {
        int n = Np[0];
        float b00 = linMt[0], b01 = linMt[1];
        float b10 = linMt[2], b11 = linMt[3];
        float p00 = 1.f, p01 = 0.f, p10 = 0.f, p11 = 1.f;
        while (n > 0) {
            if (n & 1) {
                float t00 = fmaf(p00, b00, p01 * b10);
                float t01 = fmaf(p00, b01, p01 * b11);
                float t10 = fmaf(p10, b00, p11 * b10);
                float t11 = fmaf(p10, b01, p11 * b11);
                p00 = t00; p01 = t01; p10 = t10; p11 = t11;
            }
            n >>= 1;
            if (n > 0) {
                float s00 = fmaf(b00, b00, b01 * b10);
                float s01 = fmaf(b00, b01, b01 * b11);
                float s10 = fmaf(b10, b00, b11 * b10);
                float s11 = fmaf(b10, b01, b11 * b11);
                b00 = s00; b01 = s01; b10 = s10; b11 = s11;
            }
        }
        sM[0] = p00; sM[1] = p01; sM[2] = p10; sM[3] = p11;
    }
    __syncthreads();
    const float m00 = sM[0], m01 = sM[1], m10 = sM[2], m11 = sM[3];

    // 3) Transform + store.
#pragma unroll
    for (int j = 0; j < VEC; j++) {
        int idx = base + j * 256;
        if (ok[j]) {
            float4 r;
            r.x = fmaf(v[j].x, m00, v[j].y * m10);
            r.y = fmaf(v[j].x, m01, v[j].y * m11);
            r.z = fmaf(v[j].z, m00, v[j].w * m10);
            r.w = fmaf(v[j].z, m01, v[j].w * m11);
            out[idx] = r;
        }
    }

    // Tail: at most one leftover state pair if total floats % 4 != 0.
    if (blockIdx.x == 0 && threadIdx.x == 0) {
        for (int p = n4 * 2; p < n_pairs; p++) {
            float a = xs[2 * p + 0];
            float b = xs[2 * p + 1];
            outs[2 * p + 0] = fmaf(a, m00, b * m10);
            outs[2 * p + 1] = fmaf(a, m01, b * m11);
        }
    }
}

extern "C" void kernel_launch(void* const* d_in, const int* in_sizes, int n_in,
                              void* d_out, int out_size) {
    const float* x     = (const float*)d_in[0];   // (B, 2) float32
    const float* linMt = (const float*)d_in[1];   // (2, 2) float32
    const int*   Np    = (const int*)d_in[2];     // scalar N
    float* out = (float*)d_out;

    int total   = in_sizes[0];   // B * 2 floats
    int n4      = total / 4;     // float4 chunks (2 states each)
    int n_pairs = total / 2;

    int threads = 256;
    int per_block = threads * VEC;
    int blocks = (n4 + per_block - 1) / per_block;
    if (blocks < 1) blocks = 1;

    fused_kernel<<<blocks, threads>>>((const float4*)x, (float4*)out, n4,
                                      linMt, Np, x, out, n_pairs);
}